// round 15
// baseline (speedup 1.0000x reference)
#include <cuda_runtime.h>
#include <cuda_bf16.h>
#include <cstdint>
#include <math.h>

// Sqrtm Newton-Schulz on tensor cores via mma.sync bf16 (sm_80+ PTX; harness
// PTX target is plain sm_103, which rejects tcgen05).
// Chain (verified):
//   normA = sum(x); A = x/normA; Z0 = 1.5I - 0.5A
//   Y1 = A@Z0
//   3x: ZY = 0.5*Y - 0.5*(Z@Y); Y' = Y@ZY; Z' = ZY@Z
//   T = 0.5*Y - 0.5*(Y@Z); out = (T@Y)*sqrt(normA)
// Symmetric outputs => upper triangle of 4x4 grid of 64x64 tiles (10/16);
// off-diagonal tiles emit the transposed mirror.
// fp32 = bf16 hi+lo; 3 MMAs: Ah@Bh + Ah@Bl + Al@Bh.
//
// R15: B operand loaded DIRECTLY from global (L1-cached) into mma-layout
// registers, prefetched one k-step ahead; only A goes through smem+ldmatrix.
// Removes half of all smem wavefronts (the co-binding pipe at L1~64%).
// Stage 16KB, 2 stages = 32KB smem => up to 4 CTAs/SM (launch_bounds 128,4).

#define DMAT 256
#define MSZ  65536
#define BATCH 256

#define PLANE 8192               // A: 64 rows x 128B (one plane)
#define STAGE  (2 * PLANE)       // 16 KB (Ah|Al)
#define SMEM_TOTAL (2 * STAGE)   // 32 KB

__device__ __nv_bfloat16 g_hi[5][(size_t)BATCH * MSZ];
__device__ __nv_bfloat16 g_lo[5][(size_t)BATCH * MSZ];
__device__ float g_inv[BATCH];
__device__ float g_sqrt[BATCH];

__device__ __forceinline__ uint32_t smem_u32(const void* p) {
    uint32_t a;
    asm("{ .reg .u64 t; cvta.to.shared.u64 t, %1; cvt.u32.u64 %0, t; }" : "=r"(a) : "l"(p));
    return a;
}

#define LDSM4(r, a) \
    asm volatile("ldmatrix.sync.aligned.m8n8.x4.shared.b16 {%0,%1,%2,%3}, [%4];" \
        : "=r"((r)[0]), "=r"((r)[1]), "=r"((r)[2]), "=r"((r)[3]) : "r"(a))

#define MMA(d, a, bb) \
    asm volatile("mma.sync.aligned.m16n8k16.row.col.f32.bf16.bf16.f32 " \
        "{%0,%1,%2,%3}, {%4,%5,%6,%7}, {%8,%9}, {%0,%1,%2,%3};" \
        : "+f"((d)[0]), "+f"((d)[1]), "+f"((d)[2]), "+f"((d)[3]) \
        : "r"((a)[0]), "r"((a)[1]), "r"((a)[2]), "r"((a)[3]), \
          "r"((bb)[0]), "r"((bb)[1]))

// ---------------------------------------------------------------------------
__global__ void norm_kernel(const float* __restrict__ x) {
    const int b = blockIdx.x;
    const float* p = x + (size_t)b * MSZ;
    float s = 0.f;
    for (int i = threadIdx.x; i < MSZ; i += 256) s += p[i];
    __shared__ float sh[256];
    sh[threadIdx.x] = s;
    __syncthreads();
    for (int off = 128; off > 0; off >>= 1) {
        if (threadIdx.x < off) sh[threadIdx.x] += sh[threadIdx.x + off];
        __syncthreads();
    }
    if (threadIdx.x == 0) {
        float n = sh[0];
        g_inv[b] = 1.0f / n;
        g_sqrt[b] = sqrtf(n);
    }
}

__global__ void setup_kernel(const float* __restrict__ x) {
    const size_t idx = (size_t)blockIdx.x * blockDim.x + threadIdx.x;
    const int b = (int)(idx >> 16);
    const int ij = (int)(idx & (MSZ - 1));
    const float a = x[idx] * g_inv[b];
    const int i = ij >> 8, j = ij & 255;
    const float z = (i == j ? 1.5f : 0.0f) - 0.5f * a;

    __nv_bfloat16 ah = __float2bfloat16_rn(a);
    __nv_bfloat16 al = __float2bfloat16_rn(a - __bfloat162float(ah));
    __nv_bfloat16 zh = __float2bfloat16_rn(z);
    __nv_bfloat16 zl = __float2bfloat16_rn(z - __bfloat162float(zh));
    g_hi[0][idx] = ah;  g_lo[0][idx] = al;
    g_hi[3][idx] = zh;  g_lo[3][idx] = zl;
}

// ---------------------------------------------------------------------------
// Batched GEMM step. grid = (10 tiles, BATCH). 128 threads, 4 warps (2M x 2N),
// warp tile 32x32, CTA tile 64x64. A: BK=64 smem chunks (2-stage cp.async).
// B: direct-global register fragments, prefetched one k16-step ahead.
// Tile t -> (ti, tj) upper triangle; ti<tj also writes transposed mirror.
// mode 0: C = A@B               -> hi/lo pair in buf idst
// mode 1: C = 0.5*Y - 0.5*(A@B) -> pair in buf idst   (Y = buf iy)
// mode 2: C = (A@B)*sqrt(normA) -> fp32 to outp
__global__ void __launch_bounds__(128, 4)
gemm_mma(int ia, int ib, int iy, int idst, int mode, float* __restrict__ outp)
{
    extern __shared__ __align__(128) char smem[];
    const uint32_t sbase = smem_u32(smem);
    const int tid = threadIdx.x, wid = tid >> 5, lane = tid & 31;
    const int t = blockIdx.x;
    const int b = blockIdx.y;
    const int TI[10] = {0, 0, 0, 0, 1, 1, 1, 2, 2, 3};
    const int TJ[10] = {0, 1, 2, 3, 1, 2, 3, 2, 3, 3};
    const int ti = TI[t], tj = TJ[t];
    const int mBase = ti * 64, nBase = tj * 64;
    const bool mir = (ti != tj);
    const size_t mo = (size_t)b * MSZ;

    const __nv_bfloat16* Ah = g_hi[ia] + mo;
    const __nv_bfloat16* Al = g_lo[ia] + mo;
    const __nv_bfloat16* Bh = g_hi[ib] + mo;
    const __nv_bfloat16* Bl = g_lo[ib] + mo;

    const int warpM = wid & 1;   // 2 warps over M (32 rows each)
    const int warpN = wid >> 1;  // 2 warps over N (32 cols each)

    float acc[2][4][4] = {};     // [mt][nt][frag]

    // ---- A: global -> smem (cp.async), one K-chunk of 64 cols, 2 planes ----
    auto load_chunk = [&](int stage, int c) {
        const uint32_t sb = sbase + stage * STAGE;
        const int kc = c * 64;
        #pragma unroll
        for (int it = 0; it < 8; ++it) {
            const int i = tid + it * 128;        // 0..1023
            const int plane = i >> 9;            // 0:Ah 1:Al
            const int rem = i & 511;
            const int row = rem >> 3, seg = rem & 7;
            const __nv_bfloat16* sp = plane ? Al : Ah;
            const void* src = sp + (size_t)(mBase + row) * DMAT + kc + seg * 8;
            const uint32_t dst = sb + plane * PLANE + row * 128 +
                                 ((seg ^ (row & 7)) * 16);
            asm volatile("cp.async.cg.shared.global [%0], [%1], 16;"
                         :: "r"(dst), "l"(src));
        }
        asm volatile("cp.async.commit_group;" ::: "memory");
    };

    // ---- B: direct-global fragment loads (mma B-layout), double-buffered ----
    // reg (nt, r), lane l = B[nBase + warpN*32 + nt*8 + l/4][kk + r*8 + (l&3)*2]
    uint32_t bhf[2][4][2], blf[2][4][2];
    const __nv_bfloat16* pBh =
        Bh + (size_t)(nBase + warpN * 32 + (lane >> 2)) * DMAT + (lane & 3) * 2;
    const __nv_bfloat16* pBl =
        Bl + (size_t)(nBase + warpN * 32 + (lane >> 2)) * DMAT + (lane & 3) * 2;

    auto load_B = [&](int fb, int kk) {
        #pragma unroll
        for (int nt = 0; nt < 4; ++nt) {
            const __nv_bfloat16* ph = pBh + nt * 8 * DMAT + kk;
            const __nv_bfloat16* pl = pBl + nt * 8 * DMAT + kk;
            bhf[fb][nt][0] = *(const uint32_t*)(ph);
            bhf[fb][nt][1] = *(const uint32_t*)(ph + 8);
            blf[fb][nt][0] = *(const uint32_t*)(pl);
            blf[fb][nt][1] = *(const uint32_t*)(pl + 8);
        }
    };

    const int r16 = lane & 15, chf = lane >> 4, xr = lane & 7;
    const uint32_t aRow0 = (uint32_t)(warpM * 32 + r16) * 128;

    load_chunk(0, 0);
    load_chunk(1, 1);
    load_B(0, 0);

    #pragma unroll
    for (int c = 0; c < 4; ++c) {
        if (c < 3) asm volatile("cp.async.wait_group 1;" ::: "memory");
        else       asm volatile("cp.async.wait_group 0;" ::: "memory");
        __syncthreads();
        const uint32_t sb = sbase + (uint32_t)((c & 1) * STAGE);
        #pragma unroll
        for (int ks = 0; ks < 4; ++ks) {
            const int g = c * 4 + ks;
            // A fragments from smem
            const uint32_t sw = (uint32_t)(((ks * 2 + chf) ^ xr) * 16);
            uint32_t ahf[2][4], alf[2][4];
            #pragma unroll
            for (int mt = 0; mt < 2; ++mt) {
                const uint32_t addr = sb + aRow0 + (uint32_t)(mt * 2048) + sw;
                LDSM4(ahf[mt], addr);            // plane Ah
                LDSM4(alf[mt], addr + PLANE);    // plane Al
            }
            // prefetch next k16-step's B while LDSM results land
            if (g < 15) load_B((g + 1) & 1, (g + 1) * 16);
            const int fb = g & 1;
            #pragma unroll
            for (int mt = 0; mt < 2; ++mt)
                #pragma unroll
                for (int nt = 0; nt < 4; ++nt)
                    MMA(acc[mt][nt], ahf[mt], bhf[fb][nt]);
            #pragma unroll
            for (int mt = 0; mt < 2; ++mt)
                #pragma unroll
                for (int nt = 0; nt < 4; ++nt)
                    MMA(acc[mt][nt], ahf[mt], blf[fb][nt]);
            #pragma unroll
            for (int mt = 0; mt < 2; ++mt)
                #pragma unroll
                for (int nt = 0; nt < 4; ++nt)
                    MMA(acc[mt][nt], alf[mt], bhf[fb][nt]);
        }
        __syncthreads();
        if (c < 2) load_chunk(c & 1, c + 2);
    }

    // ---- epilogue ----
    const float sc = g_sqrt[b];
    const int r4 = lane >> 2, c2 = (lane & 3) * 2;
    const __nv_bfloat16* Yh = g_hi[iy] + mo;
    const __nv_bfloat16* Yl = g_lo[iy] + mo;
    __nv_bfloat16* Dh = g_hi[idst] + mo;
    __nv_bfloat16* Dl = g_lo[idst] + mo;
    float* Of = outp + mo;
    uint32_t* sm32 = (uint32_t*)smem;   // mirror staging, pitch 65 words

    #pragma unroll
    for (int mt = 0; mt < 2; ++mt)
        #pragma unroll
        for (int nt = 0; nt < 4; ++nt)
            #pragma unroll
            for (int h = 0; h < 2; ++h) {
                const int rloc = warpM * 32 + mt * 16 + r4 + h * 8;
                const int cloc = warpN * 32 + nt * 8 + c2;
                const int row = mBase + rloc, col = nBase + cloc;
                float v0 = acc[mt][nt][h * 2];
                float v1 = acc[mt][nt][h * 2 + 1];
                const size_t off = (size_t)row * DMAT + col;
                if (mode == 1) {
                    const uint32_t hw = *(const uint32_t*)(Yh + off);
                    const uint32_t lw = *(const uint32_t*)(Yl + off);
                    const float y0 = __uint_as_float(hw << 16) +
                                     __uint_as_float(lw << 16);
                    const float y1 = __uint_as_float(hw & 0xffff0000u) +
                                     __uint_as_float(lw & 0xffff0000u);
                    v0 = 0.5f * y0 - 0.5f * v0;
                    v1 = 0.5f * y1 - 0.5f * v1;
                }
                if (mode == 2) {
                    v0 *= sc;  v1 *= sc;
                    *(float2*)(Of + off) = make_float2(v0, v1);
                    if (mir) {
                        sm32[rloc * 65 + cloc]     = __float_as_uint(v0);
                        sm32[rloc * 65 + cloc + 1] = __float_as_uint(v1);
                    }
                } else {
                    const __nv_bfloat16 h0 = __float2bfloat16_rn(v0);
                    const __nv_bfloat16 h1 = __float2bfloat16_rn(v1);
                    const __nv_bfloat16 l0 =
                        __float2bfloat16_rn(v0 - __bfloat162float(h0));
                    const __nv_bfloat16 l1 =
                        __float2bfloat16_rn(v1 - __bfloat162float(h1));
                    __nv_bfloat162 hp = __halves2bfloat162(h0, h1);
                    __nv_bfloat162 lp = __halves2bfloat162(l0, l1);
                    const uint32_t hpw = *(uint32_t*)&hp;
                    const uint32_t lpw = *(uint32_t*)&lp;
                    *(uint32_t*)(Dh + off) = hpw;
                    *(uint32_t*)(Dl + off) = lpw;
                    if (mir) {
                        // pack (hi, lo) of each element into one word
                        sm32[rloc * 65 + cloc] =
                            (hpw & 0xffffu) | (lpw << 16);
                        sm32[rloc * 65 + cloc + 1] =
                            (hpw >> 16) | (lpw & 0xffff0000u);
                    }
                }
            }

    if (mir) {
        __syncthreads();
        // mirror block: rows tj*64.., cols ti*64..
        // element (tj*64+i, ti*64+j) = local (row j, col i) = sm32[j*65+i]
        #pragma unroll
        for (int it = 0; it < 16; ++it) {
            const int e = tid + it * 128;         // 0..2047 (pairs)
            const int i = e >> 5;                 // mirror row 0..63
            const int j = (e & 31) * 2;           // mirror col, even
            const uint32_t w0 = sm32[j * 65 + i];
            const uint32_t w1 = sm32[(j + 1) * 65 + i];
            const size_t off = (size_t)(nBase + i) * DMAT + mBase + j;
            if (mode == 2) {
                *(float2*)(Of + off) =
                    make_float2(__uint_as_float(w0), __uint_as_float(w1));
            } else {
                *(uint32_t*)(Dh + off) = (w0 & 0xffffu) | (w1 << 16);
                *(uint32_t*)(Dl + off) = (w0 >> 16) | (w1 & 0xffff0000u);
            }
        }
    }
}

// ---------------------------------------------------------------------------
extern "C" void kernel_launch(void* const* d_in, const int* in_sizes, int n_in,
                              void* d_out, int out_size) {
    const float* x = (const float*)d_in[0];
    float* out = (float*)d_out;
    (void)in_sizes; (void)n_in; (void)out_size;

    cudaFuncSetAttribute(gemm_mma, cudaFuncAttributeMaxDynamicSharedMemorySize,
                         SMEM_TOTAL);

    norm_kernel<<<BATCH, 256>>>(x);
    setup_kernel<<<(BATCH * MSZ) / 256, 256>>>(x);

    dim3 grid(10, BATCH);
    #define GEMM(ia, ib, iy, idst, mode) \
        gemm_mma<<<grid, 128, SMEM_TOTAL>>>(ia, ib, iy, idst, mode, out)

    GEMM(0, 3, 0, 1, 0);   // Y1(1) = A(0)@Z0(3)
    // iter 1
    GEMM(3, 1, 1, 2, 1);   // ZY(2) = 0.5*Y(1) - 0.5*Z(3)@Y(1)
    GEMM(1, 2, 0, 0, 0);   // Y2(0) = Y(1)@ZY(2)
    GEMM(2, 3, 0, 4, 0);   // Z2(4) = ZY(2)@Z(3)
    // iter 2
    GEMM(4, 0, 0, 2, 1);   // ZY(2) = 0.5*Y(0) - 0.5*Z(4)@Y(0)
    GEMM(0, 2, 0, 1, 0);   // Y3(1) = Y(0)@ZY(2)
    GEMM(2, 4, 0, 3, 0);   // Z3(3) = ZY(2)@Z(4)
    // iter 3
    GEMM(3, 1, 1, 2, 1);   // ZY(2) = 0.5*Y(1) - 0.5*Z(3)@Y(1)
    GEMM(1, 2, 0, 0, 0);   // Y4(0) = Y(1)@ZY(2)
    GEMM(2, 3, 0, 4, 0);   // Z4(4) = ZY(2)@Z(3)
    // final
    GEMM(0, 4, 0, 2, 1);   // T(2) = 0.5*Y(0) - 0.5*Y(0)@Z(4)
    GEMM(2, 0, 0, 0, 2);   // out = T(2)@Y(0) * sqrt(normA)
    #undef GEMM
}

// round 17
// speedup vs baseline: 1.7373x; 1.7373x over previous
#include <cuda_runtime.h>
#include <cuda_bf16.h>
#include <cstdint>
#include <math.h>

// Sqrtm Newton-Schulz on tensor cores via mma.sync bf16 (sm_80+ PTX; harness
// PTX target is plain sm_103, which rejects tcgen05).
// Chain (verified):
//   normA = sum(x); A = x/normA; Z0 = 1.5I - 0.5A
//   Y1 = A@Z0
//   3x: ZY = 0.5*Y - 0.5*(Z@Y); Y' = Y@ZY; Z' = ZY@Z
//   T = 0.5*Y - 0.5*(Y@Z); out = (T@Y)*sqrt(normA)
// Symmetric outputs => upper triangle of 4x4 grid of 64x64 tiles (10/16);
// off-diagonal tiles emit the transposed mirror.
// fp32 = bf16 hi+lo; 3 MMAs: Ah@Bh + Ah@Bl + Al@Bh.
//
// R17 = R16 with CORRECTED bit-packed tile constants (R16's were shifted
// garbage -> wrong tiles -> stale-buffer nondeterminism):
//   TIP = sum ti[t]*4^t = 0x000E9500 for ti {0,0,0,0,1,1,1,2,2,3}
//   TJP = sum tj[t]*4^t = 0x000FB9E4 for tj {0,1,2,3,1,2,3,2,3,3}
// Mainloop byte-identical to R11 (806us champion); mode-1 epilogue batches
// all 16 Y hi/lo loads first (MLP) before the math.

#define DMAT 256
#define MSZ  65536
#define BATCH 256

#define PLANE 8192               // 64 rows x 128B
#define OFF_BH (2 * PLANE)
#define STAGE  (4 * PLANE)       // 32 KB
#define SMEM_TOTAL (2 * STAGE)   // 64 KB

__device__ __nv_bfloat16 g_hi[5][(size_t)BATCH * MSZ];
__device__ __nv_bfloat16 g_lo[5][(size_t)BATCH * MSZ];
__device__ float g_inv[BATCH];
__device__ float g_sqrt[BATCH];

__device__ __forceinline__ uint32_t smem_u32(const void* p) {
    uint32_t a;
    asm("{ .reg .u64 t; cvta.to.shared.u64 t, %1; cvt.u32.u64 %0, t; }" : "=r"(a) : "l"(p));
    return a;
}

#define LDSM4(r, a) \
    asm volatile("ldmatrix.sync.aligned.m8n8.x4.shared.b16 {%0,%1,%2,%3}, [%4];" \
        : "=r"((r)[0]), "=r"((r)[1]), "=r"((r)[2]), "=r"((r)[3]) : "r"(a))

#define MMA(d, a, bb) \
    asm volatile("mma.sync.aligned.m16n8k16.row.col.f32.bf16.bf16.f32 " \
        "{%0,%1,%2,%3}, {%4,%5,%6,%7}, {%8,%9}, {%0,%1,%2,%3};" \
        : "+f"((d)[0]), "+f"((d)[1]), "+f"((d)[2]), "+f"((d)[3]) \
        : "r"((a)[0]), "r"((a)[1]), "r"((a)[2]), "r"((a)[3]), \
          "r"((bb)[0]), "r"((bb)[1]))

// ---------------------------------------------------------------------------
__global__ void norm_kernel(const float* __restrict__ x) {
    const int b = blockIdx.x;
    const float* p = x + (size_t)b * MSZ;
    float s = 0.f;
    for (int i = threadIdx.x; i < MSZ; i += 256) s += p[i];
    __shared__ float sh[256];
    sh[threadIdx.x] = s;
    __syncthreads();
    for (int off = 128; off > 0; off >>= 1) {
        if (threadIdx.x < off) sh[threadIdx.x] += sh[threadIdx.x + off];
        __syncthreads();
    }
    if (threadIdx.x == 0) {
        float n = sh[0];
        g_inv[b] = 1.0f / n;
        g_sqrt[b] = sqrtf(n);
    }
}

__global__ void setup_kernel(const float* __restrict__ x) {
    const size_t idx = (size_t)blockIdx.x * blockDim.x + threadIdx.x;
    const int b = (int)(idx >> 16);
    const int ij = (int)(idx & (MSZ - 1));
    const float a = x[idx] * g_inv[b];
    const int i = ij >> 8, j = ij & 255;
    const float z = (i == j ? 1.5f : 0.0f) - 0.5f * a;

    __nv_bfloat16 ah = __float2bfloat16_rn(a);
    __nv_bfloat16 al = __float2bfloat16_rn(a - __bfloat162float(ah));
    __nv_bfloat16 zh = __float2bfloat16_rn(z);
    __nv_bfloat16 zl = __float2bfloat16_rn(z - __bfloat162float(zh));
    g_hi[0][idx] = ah;  g_lo[0][idx] = al;
    g_hi[3][idx] = zh;  g_lo[3][idx] = zl;
}

// ---------------------------------------------------------------------------
// Batched GEMM step. grid = (10 tiles, BATCH). 128 threads, 4 warps (2M x 2N),
// warp tile 32x32, CTA tile 64x64, BK=64, 4 chunks, 2-stage pipeline.
// Tile t -> (ti, tj) upper triangle; ti<tj also writes transposed mirror.
// mode 0: C = A@B               -> hi/lo pair in buf idst
// mode 1: C = 0.5*Y - 0.5*(A@B) -> pair in buf idst   (Y = buf iy)
// mode 2: C = (A@B)*sqrt(normA) -> fp32 to outp
__global__ void __launch_bounds__(128, 3)
gemm_mma(int ia, int ib, int iy, int idst, int mode, float* __restrict__ outp)
{
    extern __shared__ __align__(128) char smem[];
    const uint32_t sbase = smem_u32(smem);
    const int tid = threadIdx.x, wid = tid >> 5, lane = tid & 31;
    const int t = blockIdx.x;
    const int b = blockIdx.y;
    // bit-packed tile coords (2 bits per t), verified:
    // ti {0,0,0,0,1,1,1,2,2,3} -> 0x000E9500
    // tj {0,1,2,3,1,2,3,2,3,3} -> 0x000FB9E4
    const int ti = (int)((0x000E9500u >> (2 * t)) & 3u);
    const int tj = (int)((0x000FB9E4u >> (2 * t)) & 3u);
    const int mBase = ti * 64, nBase = tj * 64;
    const bool mir = (ti != tj);
    const size_t mo = (size_t)b * MSZ;

    const __nv_bfloat16* Ah = g_hi[ia] + mo;
    const __nv_bfloat16* Al = g_lo[ia] + mo;
    const __nv_bfloat16* Bh = g_hi[ib] + mo;
    const __nv_bfloat16* Bl = g_lo[ib] + mo;

    const int warpM = wid & 1;   // 2 warps over M (32 rows each)
    const int warpN = wid >> 1;  // 2 warps over N (32 cols each)

    float acc[2][4][4] = {};     // [mt][nt][frag]

    // ---- global -> smem (cp.async), one K-chunk of 64 cols, 4 planes ----
    auto load_chunk = [&](int stage, int c) {
        const uint32_t sb = sbase + stage * STAGE;
        const int kc = c * 64;
        #pragma unroll
        for (int it = 0; it < 16; ++it) {
            const int i = tid + it * 128;        // 0..2047
            const int plane = i >> 9;            // 0:Ah 1:Al 2:Bh 3:Bl
            const int rem = i & 511;
            const int row = rem >> 3, seg = rem & 7;
            const __nv_bfloat16* sp =
                (plane == 0) ? Ah : (plane == 1) ? Al :
                (plane == 2) ? Bh : Bl;
            const int gRow = ((plane < 2) ? mBase : nBase) + row;
            const void* src = sp + (size_t)gRow * DMAT + kc + seg * 8;
            const uint32_t dst = sb + plane * PLANE + row * 128 +
                                 ((seg ^ (row & 7)) * 16);
            asm volatile("cp.async.cg.shared.global [%0], [%1], 16;"
                         :: "r"(dst), "l"(src));
        }
        asm volatile("cp.async.commit_group;" ::: "memory");
    };

    // ---- compute one K-chunk (4 x k16 steps), 3-product split ----
    const int r16 = lane & 15, chf = lane >> 4, xr = lane & 7;
    const uint32_t aRow0 = (uint32_t)(warpM * 32 + r16) * 128;
    const uint32_t bRow0 = OFF_BH + (uint32_t)(warpN * 32 + r16) * 128;

    auto compute_chunk = [&](int stage) {
        const uint32_t sb = sbase + stage * STAGE;
        #pragma unroll
        for (int ks = 0; ks < 4; ++ks) {
            const uint32_t sw = (uint32_t)(((ks * 2 + chf) ^ xr) * 16);
            uint32_t ahf[2][4], alf[2][4], bhf[4][2], blf[4][2];
            #pragma unroll
            for (int mt = 0; mt < 2; ++mt) {
                const uint32_t addr = sb + aRow0 + (uint32_t)(mt * 2048) + sw;
                LDSM4(ahf[mt], addr);            // plane Ah
                LDSM4(alf[mt], addr + PLANE);    // plane Al
            }
            #pragma unroll
            for (int np = 0; np < 2; ++np) {
                const uint32_t addr = sb + bRow0 + (uint32_t)(np * 2048) + sw;
                uint32_t tt[4];
                LDSM4(tt, addr);                 // plane Bh
                bhf[np * 2][0] = tt[0];      bhf[np * 2][1] = tt[2];
                bhf[np * 2 + 1][0] = tt[1];  bhf[np * 2 + 1][1] = tt[3];
                LDSM4(tt, addr + PLANE);         // plane Bl
                blf[np * 2][0] = tt[0];      blf[np * 2][1] = tt[2];
                blf[np * 2 + 1][0] = tt[1];  blf[np * 2 + 1][1] = tt[3];
            }
            #pragma unroll
            for (int mt = 0; mt < 2; ++mt)
                #pragma unroll
                for (int nt = 0; nt < 4; ++nt)
                    MMA(acc[mt][nt], ahf[mt], bhf[nt]);
            #pragma unroll
            for (int mt = 0; mt < 2; ++mt)
                #pragma unroll
                for (int nt = 0; nt < 4; ++nt)
                    MMA(acc[mt][nt], ahf[mt], blf[nt]);
            #pragma unroll
            for (int mt = 0; mt < 2; ++mt)
                #pragma unroll
                for (int nt = 0; nt < 4; ++nt)
                    MMA(acc[mt][nt], alf[mt], bhf[nt]);
        }
    };

    load_chunk(0, 0);
    load_chunk(1, 1);
    #pragma unroll
    for (int c = 0; c < 4; ++c) {
        if (c < 3) asm volatile("cp.async.wait_group 1;" ::: "memory");
        else       asm volatile("cp.async.wait_group 0;" ::: "memory");
        __syncthreads();
        compute_chunk(c & 1);
        __syncthreads();
        if (c < 2) load_chunk(c & 1, c + 2);
    }

    // ---- epilogue ----
    const float sc = g_sqrt[b];
    const int r4 = lane >> 2, c2 = (lane & 3) * 2;
    const __nv_bfloat16* Yh = g_hi[iy] + mo;
    const __nv_bfloat16* Yl = g_lo[iy] + mo;
    __nv_bfloat16* Dh = g_hi[idst] + mo;
    __nv_bfloat16* Dl = g_lo[idst] + mo;
    float* Of = outp + mo;
    uint32_t* sm32 = (uint32_t*)smem;   // mirror staging, pitch 65 words

    // mode-1: batch ALL Y hi/lo loads first (16-deep MLP), then math.
    uint32_t yhw[16], ylw[16];
    if (mode == 1) {
        #pragma unroll
        for (int mt = 0; mt < 2; ++mt)
            #pragma unroll
            for (int nt = 0; nt < 4; ++nt)
                #pragma unroll
                for (int h = 0; h < 2; ++h) {
                    const int row = mBase + warpM * 32 + mt * 16 + r4 + h * 8;
                    const int col = nBase + warpN * 32 + nt * 8 + c2;
                    const size_t off = (size_t)row * DMAT + col;
                    const int q = (mt * 4 + nt) * 2 + h;
                    yhw[q] = *(const uint32_t*)(Yh + off);
                    ylw[q] = *(const uint32_t*)(Yl + off);
                }
    }

    #pragma unroll
    for (int mt = 0; mt < 2; ++mt)
        #pragma unroll
        for (int nt = 0; nt < 4; ++nt)
            #pragma unroll
            for (int h = 0; h < 2; ++h) {
                const int rloc = warpM * 32 + mt * 16 + r4 + h * 8;
                const int cloc = warpN * 32 + nt * 8 + c2;
                const int row = mBase + rloc, col = nBase + cloc;
                float v0 = acc[mt][nt][h * 2];
                float v1 = acc[mt][nt][h * 2 + 1];
                const size_t off = (size_t)row * DMAT + col;
                if (mode == 1) {
                    const int q = (mt * 4 + nt) * 2 + h;
                    const uint32_t hw = yhw[q], lw = ylw[q];
                    const float y0 = __uint_as_float(hw << 16) +
                                     __uint_as_float(lw << 16);
                    const float y1 = __uint_as_float(hw & 0xffff0000u) +
                                     __uint_as_float(lw & 0xffff0000u);
                    v0 = 0.5f * y0 - 0.5f * v0;
                    v1 = 0.5f * y1 - 0.5f * v1;
                }
                if (mode == 2) {
                    v0 *= sc;  v1 *= sc;
                    *(float2*)(Of + off) = make_float2(v0, v1);
                    if (mir) {
                        sm32[rloc * 65 + cloc]     = __float_as_uint(v0);
                        sm32[rloc * 65 + cloc + 1] = __float_as_uint(v1);
                    }
                } else {
                    const __nv_bfloat16 h0 = __float2bfloat16_rn(v0);
                    const __nv_bfloat16 h1 = __float2bfloat16_rn(v1);
                    const __nv_bfloat16 l0 =
                        __float2bfloat16_rn(v0 - __bfloat162float(h0));
                    const __nv_bfloat16 l1 =
                        __float2bfloat16_rn(v1 - __bfloat162float(h1));
                    __nv_bfloat162 hp = __halves2bfloat162(h0, h1);
                    __nv_bfloat162 lp = __halves2bfloat162(l0, l1);
                    const uint32_t hpw = *(uint32_t*)&hp;
                    const uint32_t lpw = *(uint32_t*)&lp;
                    *(uint32_t*)(Dh + off) = hpw;
                    *(uint32_t*)(Dl + off) = lpw;
                    if (mir) {
                        // pack (hi, lo) of each element into one word
                        sm32[rloc * 65 + cloc] =
                            (hpw & 0xffffu) | (lpw << 16);
                        sm32[rloc * 65 + cloc + 1] =
                            (hpw >> 16) | (lpw & 0xffff0000u);
                    }
                }
            }

    if (mir) {
        __syncthreads();
        // mirror block: rows tj*64.., cols ti*64..
        // element (tj*64+i, ti*64+j) = local (row j, col i) = sm32[j*65+i]
        #pragma unroll
        for (int it = 0; it < 16; ++it) {
            const int e = tid + it * 128;         // 0..2047 (pairs)
            const int i = e >> 5;                 // mirror row 0..63
            const int j = (e & 31) * 2;           // mirror col, even
            const uint32_t w0 = sm32[j * 65 + i];
            const uint32_t w1 = sm32[(j + 1) * 65 + i];
            const size_t off = (size_t)(nBase + i) * DMAT + mBase + j;
            if (mode == 2) {
                *(float2*)(Of + off) =
                    make_float2(__uint_as_float(w0), __uint_as_float(w1));
            } else {
                *(uint32_t*)(Dh + off) = (w0 & 0xffffu) | (w1 << 16);
                *(uint32_t*)(Dl + off) = (w0 >> 16) | (w1 & 0xffff0000u);
            }
        }
    }
}

// ---------------------------------------------------------------------------
extern "C" void kernel_launch(void* const* d_in, const int* in_sizes, int n_in,
                              void* d_out, int out_size) {
    const float* x = (const float*)d_in[0];
    float* out = (float*)d_out;
    (void)in_sizes; (void)n_in; (void)out_size;

    cudaFuncSetAttribute(gemm_mma, cudaFuncAttributeMaxDynamicSharedMemorySize,
                         SMEM_TOTAL);

    norm_kernel<<<BATCH, 256>>>(x);
    setup_kernel<<<(BATCH * MSZ) / 256, 256>>>(x);

    dim3 grid(10, BATCH);
    #define GEMM(ia, ib, iy, idst, mode) \
        gemm_mma<<<grid, 128, SMEM_TOTAL>>>(ia, ib, iy, idst, mode, out)

    GEMM(0, 3, 0, 1, 0);   // Y1(1) = A(0)@Z0(3)
    // iter 1
    GEMM(3, 1, 1, 2, 1);   // ZY(2) = 0.5*Y(1) - 0.5*Z(3)@Y(1)
    GEMM(1, 2, 0, 0, 0);   // Y2(0) = Y(1)@ZY(2)
    GEMM(2, 3, 0, 4, 0);   // Z2(4) = ZY(2)@Z(3)
    // iter 2
    GEMM(4, 0, 0, 2, 1);   // ZY(2) = 0.5*Y(0) - 0.5*Z(4)@Y(0)
    GEMM(0, 2, 0, 1, 0);   // Y3(1) = Y(0)@ZY(2)
    GEMM(2, 4, 0, 3, 0);   // Z3(3) = ZY(2)@Z(4)
    // iter 3
    GEMM(3, 1, 1, 2, 1);   // ZY(2) = 0.5*Y(1) - 0.5*Z(3)@Y(1)
    GEMM(1, 2, 0, 0, 0);   // Y4(0) = Y(1)@ZY(2)
    GEMM(2, 3, 0, 4, 0);   // Z4(4) = ZY(2)@Z(3)
    // final
    GEMM(0, 4, 0, 2, 1);   // T(2) = 0.5*Y(0) - 0.5*Y(0)@Z(4)
    GEMM(2, 0, 0, 0, 2);   // out = T(2)@Y(0) * sqrt(normA)
    #undef GEMM
}